// round 1
// baseline (speedup 1.0000x reference)
#include <cuda_runtime.h>
#include <cstdint>
#include <cstddef>
#include <math.h>

#define T    60
#define NN   10000
#define EE   160000
#define INC  64
#define HIDC 128

// ---------------- scratch (static device globals; no allocation) ----------------
__device__ int      g_deg [T * NN];
__device__ int      g_off [T * NN];
__device__ int      g_cur [T * NN];
__device__ int      g_esrc[(size_t)T * EE];
__device__ float    g_mean[(size_t)T * NN * INC];   // 153.6 MB
__device__ float    g_p   [(size_t)T * NN * 8];     // layer-2 aggregand (padded to 8)
__device__ float    g_rr  [(size_t)T * NN * 8];     // self term of layer 2
__device__ unsigned g_zenc[T * 8];                  // ordered-encoded max per (t, ch)

// ordered float <-> uint encoding for atomicMax
__device__ __forceinline__ unsigned encf(float f) {
    unsigned u = __float_as_uint(f);
    return (u & 0x80000000u) ? ~u : (u | 0x80000000u);
}
__device__ __forceinline__ float decf(unsigned u) {
    return (u & 0x80000000u) ? __uint_as_float(u & 0x7fffffffu) : __uint_as_float(~u);
}

// ---------------- K0: init ----------------
__global__ void k0_init() {
    int idx = blockIdx.x * blockDim.x + threadIdx.x;
    if (idx < T * NN) g_deg[idx] = 0;
    if (idx < T * 8)  g_zenc[idx] = 0u;   // 0 < enc(any finite float incl. -inf path)
}

// ---------------- K1: degree histogram ----------------
__global__ void k1_hist(const int* __restrict__ ei) {
    int idx = blockIdx.x * blockDim.x + threadIdx.x;
    if (idx >= T * EE) return;
    int t = idx / EE;
    int e = idx - t * EE;
    int dst = ei[(size_t)t * 2 * EE + EE + e];
    atomicAdd(&g_deg[t * NN + dst], 1);
}

// ---------------- K2: per-t exclusive scan (block per t) ----------------
__global__ void k2_scan() {
    int t = blockIdx.x;
    __shared__ int s[1024];
    __shared__ int carry;
    int tid = threadIdx.x;
    if (tid == 0) carry = 0;
    __syncthreads();
    for (int base = 0; base < NN; base += 1024) {
        int i = base + tid;
        int v = (i < NN) ? g_deg[t * NN + i] : 0;
        s[tid] = v;
        __syncthreads();
        for (int off = 1; off < 1024; off <<= 1) {
            int add = (tid >= off) ? s[tid - off] : 0;
            __syncthreads();
            s[tid] += add;
            __syncthreads();
        }
        int c = carry;
        if (i < NN) {
            int excl = c + s[tid] - v;
            g_off[t * NN + i] = excl;
            g_cur[t * NN + i] = excl;
        }
        __syncthreads();
        if (tid == 0) carry = c + s[1023];
        __syncthreads();
    }
}

// ---------------- K3: scatter srcs into CSR buckets ----------------
__global__ void k3_scatter(const int* __restrict__ ei) {
    int idx = blockIdx.x * blockDim.x + threadIdx.x;
    if (idx >= T * EE) return;
    int t = idx / EE;
    int e = idx - t * EE;
    int src = ei[(size_t)t * 2 * EE + e];
    int dst = ei[(size_t)t * 2 * EE + EE + e];
    int pos = atomicAdd(&g_cur[t * NN + dst], 1);
    g_esrc[(size_t)t * EE + pos] = src;
}

// ---------------- K4a: layer-1 mean aggregation (warp per node) ----------------
__global__ void k4a_agg(const float* __restrict__ x) {
    int w = (blockIdx.x * blockDim.x + threadIdx.x) >> 5;
    int lane = threadIdx.x & 31;
    if (w >= T * NN) return;
    int node = w;
    int t = node / NN;
    int off = g_off[node];
    int deg = g_deg[node];
    const int* elist = g_esrc + (size_t)t * EE + off;
    const float* xt = x + (size_t)t * NN * INC;
    float sx = 0.f, sy = 0.f;
    int e = 0;
    for (; e + 4 <= deg; e += 4) {
        int s0 = elist[e + 0], s1 = elist[e + 1], s2 = elist[e + 2], s3 = elist[e + 3];
        float2 v0 = ((const float2*)(xt + (size_t)s0 * INC))[lane];
        float2 v1 = ((const float2*)(xt + (size_t)s1 * INC))[lane];
        float2 v2 = ((const float2*)(xt + (size_t)s2 * INC))[lane];
        float2 v3 = ((const float2*)(xt + (size_t)s3 * INC))[lane];
        sx += (v0.x + v1.x) + (v2.x + v3.x);
        sy += (v0.y + v1.y) + (v2.y + v3.y);
    }
    for (; e < deg; e++) {
        int s0 = elist[e];
        float2 v0 = ((const float2*)(xt + (size_t)s0 * INC))[lane];
        sx += v0.x; sy += v0.y;
    }
    float inv = 1.0f / (float)max(deg, 1);
    ((float2*)(g_mean + (size_t)node * INC))[lane] = make_float2(sx * inv, sy * inv);
}

// ---------------- K4b: fused GEMM1(+relu) + layer-2 projections p/rr ----------------
// h = relu(mean@W1l.T + b1 + x@W1r.T); p = h@W2l.T; rr = h@W2r.T
__global__ __launch_bounds__(256, 2) void k4b_gemm(
    const float* __restrict__ x,
    const float* __restrict__ W1l, const float* __restrict__ W1r,
    const float* __restrict__ b1,
    const float* __restrict__ W2l, const float* __restrict__ W2r)
{
    extern __shared__ float sm[];
    float* sWL = sm;                    // [c=64][o=128]  W1l transposed
    float* sWR = sm + 64 * 128;         // [c][o]         W1r transposed
    float* sB1 = sWR + 64 * 128;        // [128]
    float* sMX = sB1 + 128;             // 8 warps * (4 nodes * 2 * 64)
    int tid = threadIdx.x;
    for (int idx = tid; idx < 64 * 128; idx += 256) {
        int c = idx >> 7, o = idx & 127;
        sWL[idx] = W1l[o * 64 + c];
        sWR[idx] = W1r[o * 64 + c];
    }
    if (tid < 128) sB1[tid] = b1[tid];
    __syncthreads();

    int lane = tid & 31;
    int wid  = tid >> 5;
    // per-lane W2 slices (outputs o = 4*lane + k)
    float w2l[6][4], w2r[6][4];
#pragma unroll
    for (int j = 0; j < 6; j++)
#pragma unroll
        for (int k = 0; k < 4; k++) {
            w2l[j][k] = W2l[j * 128 + 4 * lane + k];
            w2r[j][k] = W2r[j * 128 + 4 * lane + k];
        }
    float b1r[4];
#pragma unroll
    for (int k = 0; k < 4; k++) b1r[k] = sB1[4 * lane + k];

    float* myMX = sMX + wid * 512;      // [mean: 4*64][x: 4*64]
    const float4* WL4 = (const float4*)sWL;
    const float4* WR4 = (const float4*)sWR;

    int warpGlobal = blockIdx.x * 8 + wid;
    int nWarps = gridDim.x * 8;
    const int nGroups = T * NN / 4;

    for (int g = warpGlobal; g < nGroups; g += nWarps) {
        int n0 = g * 4;
        // stage mean + x rows for 4 nodes
#pragma unroll
        for (int nn = 0; nn < 4; nn++) {
            int node = n0 + nn;
            float2 mv = ((const float2*)(g_mean + (size_t)node * INC))[lane];
            float2 xv = ((const float2*)(x + (size_t)node * INC))[lane];
            ((float2*)(myMX + nn * 64))[lane]       = mv;
            ((float2*)(myMX + 256 + nn * 64))[lane] = xv;
        }
        __syncwarp();

        float acc[4][4];
#pragma unroll
        for (int nn = 0; nn < 4; nn++)
#pragma unroll
            for (int k = 0; k < 4; k++) acc[nn][k] = b1r[k];

#pragma unroll 8
        for (int c = 0; c < 64; c++) {
            float4 wl = WL4[c * 32 + lane];
            float4 wr = WR4[c * 32 + lane];
#pragma unroll
            for (int nn = 0; nn < 4; nn++) {
                float m  = myMX[nn * 64 + c];
                float xv = myMX[256 + nn * 64 + c];
                acc[nn][0] += wl.x * m + wr.x * xv;
                acc[nn][1] += wl.y * m + wr.y * xv;
                acc[nn][2] += wl.z * m + wr.z * xv;
                acc[nn][3] += wl.w * m + wr.w * xv;
            }
        }

#pragma unroll
        for (int nn = 0; nn < 4; nn++) {
            float h0 = fmaxf(acc[nn][0], 0.f);
            float h1 = fmaxf(acc[nn][1], 0.f);
            float h2 = fmaxf(acc[nn][2], 0.f);
            float h3 = fmaxf(acc[nn][3], 0.f);
            float pl[6], pr[6];
#pragma unroll
            for (int j = 0; j < 6; j++) {
                pl[j] = h0 * w2l[j][0] + h1 * w2l[j][1] + h2 * w2l[j][2] + h3 * w2l[j][3];
                pr[j] = h0 * w2r[j][0] + h1 * w2r[j][1] + h2 * w2r[j][2] + h3 * w2r[j][3];
            }
#pragma unroll
            for (int o = 16; o > 0; o >>= 1) {
#pragma unroll
                for (int j = 0; j < 6; j++) {
                    pl[j] += __shfl_xor_sync(0xffffffffu, pl[j], o);
                    pr[j] += __shfl_xor_sync(0xffffffffu, pr[j], o);
                }
            }
            if (lane == 0) {
                size_t base = (size_t)(n0 + nn) * 8;
#pragma unroll
                for (int j = 0; j < 6; j++) {
                    g_p[base + j]  = pl[j];
                    g_rr[base + j] = pr[j];
                }
            }
        }
    }
}

// ---------------- K6: layer-2 aggregation (6 ch) + global max pool ----------------
__global__ void k6_layer2(const float* __restrict__ b2) {
    int t = blockIdx.x / 40;
    int chunk = blockIdx.x % 40;
    int i = chunk * 256 + threadIdx.x;
    __shared__ unsigned zmax[6];
    if (threadIdx.x < 6) zmax[threadIdx.x] = 0u;
    __syncthreads();
    if (i < NN) {
        int node = t * NN + i;
        int off = g_off[node], deg = g_deg[node];
        const int* elist = g_esrc + (size_t)t * EE + off;
        float s0=0,s1=0,s2=0,s3=0,s4=0,s5=0;
        for (int e = 0; e < deg; e++) {
            int src = elist[e];
            const float4* pp = (const float4*)(g_p + (size_t)(t * NN + src) * 8);
            float4 a = pp[0];
            float4 b = pp[1];
            s0 += a.x; s1 += a.y; s2 += a.z; s3 += a.w; s4 += b.x; s5 += b.y;
        }
        float inv = 1.0f / (float)max(deg, 1);
        size_t base = (size_t)node * 8;
        float v0 = s0 * inv + b2[0] + g_rr[base + 0];
        float v1 = s1 * inv + b2[1] + g_rr[base + 1];
        float v2 = s2 * inv + b2[2] + g_rr[base + 2];
        float v3 = s3 * inv + b2[3] + g_rr[base + 3];
        float v4 = s4 * inv + b2[4] + g_rr[base + 4];
        float v5 = s5 * inv + b2[5] + g_rr[base + 5];
        atomicMax(&zmax[0], encf(v0));
        atomicMax(&zmax[1], encf(v1));
        atomicMax(&zmax[2], encf(v2));
        atomicMax(&zmax[3], encf(v3));
        atomicMax(&zmax[4], encf(v4));
        atomicMax(&zmax[5], encf(v5));
    }
    __syncthreads();
    if (threadIdx.x < 6) atomicMax(&g_zenc[t * 8 + threadIdx.x], zmax[threadIdx.x]);
}

// ---------------- K7: GRU + NCE + outputs (single block) ----------------
__global__ void k7_final(const float* __restrict__ wih,
                         const float* __restrict__ bih,
                         const float* __restrict__ bhh,
                         float* __restrict__ out, int out_size)
{
    __shared__ float z[T * 6];
    __shared__ float gout[30 * 6];
    __shared__ float redf[256];
    __shared__ int   redi[256];
    int tid = threadIdx.x;
    for (int idx = tid; idx < T * 6; idx += 256)
        z[idx] = decf(g_zenc[(idx / 6) * 8 + (idx % 6)]);
    __syncthreads();
    if (tid < 180) {
        int t = tid / 6, j = tid % 6;
        float ar = 0.f, au = 0.f, an = 0.f;
#pragma unroll
        for (int d = 0; d < 6; d++) {
            float zv = z[t * 6 + d];
            ar += zv * wih[(0 + j) * 6 + d];
            au += zv * wih[(6 + j) * 6 + d];
            an += zv * wih[(12 + j) * 6 + d];
        }
        float r = 1.f / (1.f + expf(-(ar + bih[j]      + bhh[j])));
        float u = 1.f / (1.f + expf(-(au + bih[6 + j]  + bhh[6 + j])));
        float n = tanhf(an + bih[12 + j] + r * bhh[12 + j]);
        gout[tid] = (1.f - u) * n;
    }
    __syncthreads();
    float lnce = 0.f; int lc = 0;
    if (tid < 240) {
        int tp = tid / 12;           // 0..19
        int ii = tid % 12 + 1;       // 1..12
        int t = 10 + tp;
        const int joff[8] = {0, 11, 12, 13, 14, 15, 16, 17};
        float lg[8];
#pragma unroll
        for (int s = 0; s < 8; s++) {
            int idx = t + ii + joff[s];
            float d = 0.f;
#pragma unroll
            for (int c = 0; c < 6; c++) d += z[idx * 6 + c] * gout[t * 6 + c];
            lg[s] = d;
        }
        float m = lg[0];
#pragma unroll
        for (int s = 1; s < 8; s++) m = fmaxf(m, lg[s]);
        float se = 0.f;
#pragma unroll
        for (int s = 0; s < 8; s++) se += expf(lg[s] - m);
        lnce = lg[0] - m - logf(se);
        bool ok = true;
#pragma unroll
        for (int s = 1; s < 8; s++) if (lg[s] > lg[0]) ok = false;
        lc = ok ? 1 : 0;
    }
    redf[tid] = lnce; redi[tid] = lc;
    __syncthreads();
    for (int o = 128; o > 0; o >>= 1) {
        if (tid < o) { redf[tid] += redf[tid + o]; redi[tid] += redi[tid + o]; }
        __syncthreads();
    }
    if (tid == 0) {
        if (out_size > 0) out[0] = redf[0] / (-240.0f);
        if (out_size > 1) out[1] = (float)redi[0] / 240.0f;
    }
    if (tid < 180 && (2 + tid) < out_size) out[2 + tid] = gout[tid];
    for (int idx = 182 + tid; idx < out_size; idx += 256) out[idx] = 0.f;
}

// ---------------- launch ----------------
extern "C" void kernel_launch(void* const* d_in, const int* in_sizes, int n_in,
                              void* d_out, int out_size)
{
    const float* x   = (const float*)d_in[0];
    const int*   ei  = (const int*)  d_in[1];
    const float* W1l = (const float*)d_in[2];
    const float* W1r = (const float*)d_in[3];
    const float* b1  = (const float*)d_in[4];
    const float* W2l = (const float*)d_in[5];
    const float* W2r = (const float*)d_in[6];
    const float* b2  = (const float*)d_in[7];
    const float* wih = (const float*)d_in[8];
    // d_in[9] = gru_whh (unused: h0 == 0)
    const float* bih = (const float*)d_in[10];
    const float* bhh = (const float*)d_in[11];
    float* out = (float*)d_out;

    const int smemK4b = (64 * 128 * 2 + 128 + 8 * 512) * (int)sizeof(float); // 82432 B
    cudaFuncSetAttribute(k4b_gemm, cudaFuncAttributeMaxDynamicSharedMemorySize, smemK4b);

    k0_init  <<<(T * NN + 255) / 256, 256>>>();
    k1_hist  <<<(T * EE + 255) / 256, 256>>>(ei);
    k2_scan  <<<T, 1024>>>();
    k3_scatter<<<(T * EE + 255) / 256, 256>>>(ei);
    k4a_agg  <<<(T * NN * 32 + 255) / 256, 256>>>(x);
    k4b_gemm <<<296, 256, smemK4b>>>(x, W1l, W1r, b1, W2l, W2r);
    k6_layer2<<<T * ((NN + 255) / 256), 256>>>(b2);
    k7_final <<<1, 256>>>(wih, bih, bhh, out, out_size);
}